// round 5
// baseline (speedup 1.0000x reference)
#include <cuda_runtime.h>

#define NN   100000
#define NE   800000
#define IND  128
#define HID  256
#define OUTD 40
#define NB1  98   // ceil(NN/1024)

// ---------------- scratch (static __device__ per harness rules) ----------------
__device__ int   g_cnt[NN];
__device__ int   g_rowptr[NN + 1];
__device__ int   g_cursor[NN];
__device__ int   g_col[NE];
__device__ float g_dinv[NN];
__device__ int   g_bsum[NB1];
__device__ int   g_boff[NB1];
__device__ float g_ht[(size_t)NN * HID];   // (x@W1)*dinv[row]
__device__ float g_a1[(size_t)NN * HID];   // layer-1 activations
__device__ float g_h2t[(size_t)NN * OUTD]; // (a1@W2)*dinv[row]

// ---------------- degree / CSR construction ----------------
__global__ void k_zero() {
    int i = blockIdx.x * blockDim.x + threadIdx.x;
    if (i < NN) g_cnt[i] = 0;
}

__global__ void k_count(const int* __restrict__ dst) {
    int e = blockIdx.x * blockDim.x + threadIdx.x;
    if (e < NE) atomicAdd(&g_cnt[dst[e]], 1);
}

__global__ void k_scan_reduce() {
    int i = blockIdx.x * 1024 + threadIdx.x;
    int v = (i < NN) ? g_cnt[i] : 0;
    #pragma unroll
    for (int d = 16; d; d >>= 1) v += __shfl_down_sync(0xffffffffu, v, d);
    __shared__ int sm[32];
    int lane = threadIdx.x & 31, wid = threadIdx.x >> 5;
    if (lane == 0) sm[wid] = v;
    __syncthreads();
    if (wid == 0) {
        int w = sm[lane];
        #pragma unroll
        for (int d = 16; d; d >>= 1) w += __shfl_down_sync(0xffffffffu, w, d);
        if (lane == 0) g_bsum[blockIdx.x] = w;
    }
}

__global__ void k_scan_mid() {
    __shared__ int sm[NB1];
    int t = threadIdx.x;
    if (t < NB1) sm[t] = g_bsum[t];
    __syncthreads();
    if (t == 0) {
        int run = 0;
        for (int i = 0; i < NB1; i++) { int c = sm[i]; sm[i] = run; run += c; }
        g_rowptr[NN] = run;
    }
    __syncthreads();
    if (t < NB1) g_boff[t] = sm[t];
}

__global__ void k_scan_final() {
    int i = blockIdx.x * 1024 + threadIdx.x;
    int lane = threadIdx.x & 31, wid = threadIdx.x >> 5;
    int c = (i < NN) ? g_cnt[i] : 0;
    int v = c;
    #pragma unroll
    for (int d = 1; d < 32; d <<= 1) {
        int t = __shfl_up_sync(0xffffffffu, v, d);
        if (lane >= d) v += t;
    }
    __shared__ int ws[32];
    if (lane == 31) ws[wid] = v;
    __syncthreads();
    if (wid == 0) {
        int w = ws[lane];
        #pragma unroll
        for (int d = 1; d < 32; d <<= 1) {
            int t = __shfl_up_sync(0xffffffffu, w, d);
            if (lane >= d) w += t;
        }
        ws[lane] = w;
    }
    __syncthreads();
    int woff = wid ? ws[wid - 1] : 0;
    int excl = v - c + woff + g_boff[blockIdx.x];
    if (i < NN) {
        g_rowptr[i] = excl;
        g_cursor[i] = excl;
        g_dinv[i]   = rsqrtf((float)(c + 1));  // +1 self-loop, deg >= 1
    }
}

__global__ void k_fill(const int* __restrict__ src, const int* __restrict__ dst) {
    int e = blockIdx.x * blockDim.x + threadIdx.x;
    if (e < NE) {
        int d = dst[e];
        int p = atomicAdd(&g_cursor[d], 1);
        g_col[p] = src[e];
    }
}

// ---------------- GEMM1: ht = (X @ W1) * dinv[row]  [NN,128]@[128,256] ----------------
__global__ __launch_bounds__(256) void k_gemm1(const float* __restrict__ X,
                                               const float* __restrict__ W1) {
    __shared__ float As[128][32];   // [m][k]
    __shared__ float Bs[32][128];   // [k][n]
    const int m0 = blockIdx.x * 128;
    const int n0 = blockIdx.y * 128;
    const int tid = threadIdx.x;
    const int trow = tid >> 4;   // 0..15, 8 rows each
    const int tcol = tid & 15;   // 0..15, 8 cols each

    float acc[8][8];
    #pragma unroll
    for (int i = 0; i < 8; i++)
        #pragma unroll
        for (int j = 0; j < 8; j++) acc[i][j] = 0.f;

    for (int kc = 0; kc < IND; kc += 32) {
        #pragma unroll
        for (int i = 0; i < 4; i++) {
            int ff = tid + i * 256;
            int r = ff >> 3, c4 = ff & 7;
            int m = m0 + r;
            float4 v = make_float4(0.f, 0.f, 0.f, 0.f);
            if (m < NN) v = *(const float4*)(X + (size_t)m * IND + kc + c4 * 4);
            *(float4*)&As[r][c4 * 4] = v;
        }
        #pragma unroll
        for (int i = 0; i < 4; i++) {
            int ff = tid + i * 256;
            int r = ff >> 5, c4 = ff & 31;
            *(float4*)&Bs[r][c4 * 4] =
                *(const float4*)(W1 + (size_t)(kc + r) * HID + n0 + c4 * 4);
        }
        __syncthreads();

        #pragma unroll
        for (int kk = 0; kk < 32; kk++) {
            float a[8], b[8];
            #pragma unroll
            for (int i = 0; i < 8; i++) a[i] = As[trow * 8 + i][kk];
            *(float4*)&b[0] = *(float4*)&Bs[kk][tcol * 8];
            *(float4*)&b[4] = *(float4*)&Bs[kk][tcol * 8 + 4];
            #pragma unroll
            for (int i = 0; i < 8; i++)
                #pragma unroll
                for (int j = 0; j < 8; j++) acc[i][j] = fmaf(a[i], b[j], acc[i][j]);
        }
        __syncthreads();
    }

    #pragma unroll
    for (int i = 0; i < 8; i++) {
        int m = m0 + trow * 8 + i;
        if (m < NN) {
            float di = g_dinv[m];
            float4 o0, o1;
            o0.x = acc[i][0] * di; o0.y = acc[i][1] * di;
            o0.z = acc[i][2] * di; o0.w = acc[i][3] * di;
            o1.x = acc[i][4] * di; o1.y = acc[i][5] * di;
            o1.z = acc[i][6] * di; o1.w = acc[i][7] * di;
            float* outp = g_ht + (size_t)m * HID + n0 + tcol * 8;
            *(float4*)(outp)     = o0;
            *(float4*)(outp + 4) = o1;
        }
    }
}

// ---------------- agg1: a1 = relu(dinv[d]*(ht[d] + sum_in ht[s]) + b1) ----------------
__global__ __launch_bounds__(256) void k_agg1(const float* __restrict__ b1) {
    int gw = (blockIdx.x * 256 + threadIdx.x) >> 5;
    int lane = threadIdx.x & 31;
    if (gw >= NN) return;

    const float4* self = (const float4*)(g_ht + (size_t)gw * HID);
    float4 a0 = self[lane];
    float4 a1v = self[lane + 32];

    int beg = g_rowptr[gw], end = g_rowptr[gw + 1];
    for (int e = beg; e < end; e++) {
        int s = g_col[e];
        const float4* p = (const float4*)(g_ht + (size_t)s * HID);
        float4 x0 = p[lane];
        float4 x1 = p[lane + 32];
        a0.x += x0.x; a0.y += x0.y; a0.z += x0.z; a0.w += x0.w;
        a1v.x += x1.x; a1v.y += x1.y; a1v.z += x1.z; a1v.w += x1.w;
    }

    float di = g_dinv[gw];
    float4 bb0 = ((const float4*)b1)[lane];
    float4 bb1 = ((const float4*)b1)[lane + 32];
    float4 o0, o1;
    o0.x = fmaxf(fmaf(di, a0.x, bb0.x), 0.f);
    o0.y = fmaxf(fmaf(di, a0.y, bb0.y), 0.f);
    o0.z = fmaxf(fmaf(di, a0.z, bb0.z), 0.f);
    o0.w = fmaxf(fmaf(di, a0.w, bb0.w), 0.f);
    o1.x = fmaxf(fmaf(di, a1v.x, bb1.x), 0.f);
    o1.y = fmaxf(fmaf(di, a1v.y, bb1.y), 0.f);
    o1.z = fmaxf(fmaf(di, a1v.z, bb1.z), 0.f);
    o1.w = fmaxf(fmaf(di, a1v.w, bb1.w), 0.f);

    float4* outp = (float4*)(g_a1 + (size_t)gw * HID);
    outp[lane] = o0;
    outp[lane + 32] = o1;
}

// ---------------- GEMM2: h2t = (a1 @ W2) * dinv[row]  [NN,256]@[256,40] ----------------
__global__ __launch_bounds__(256) void k_gemm2(const float* __restrict__ W2) {
    __shared__ float As[128][36];   // pad 4 floats: conflict-free + 16B aligned rows
    __shared__ float Bs[32][40];
    const int m0 = blockIdx.x * 128;
    const int tid = threadIdx.x;
    const int trow = tid >> 3;   // 0..31, 4 rows each
    const int tcol = tid & 7;    // 0..7, 5 cols each

    float acc[4][5];
    #pragma unroll
    for (int i = 0; i < 4; i++)
        #pragma unroll
        for (int j = 0; j < 5; j++) acc[i][j] = 0.f;

    for (int kc = 0; kc < HID; kc += 32) {
        #pragma unroll
        for (int i = 0; i < 4; i++) {
            int ff = tid + i * 256;
            int r = ff >> 3, c4 = ff & 7;
            int m = m0 + r;
            float4 v = make_float4(0.f, 0.f, 0.f, 0.f);
            if (m < NN) v = *(const float4*)(g_a1 + (size_t)m * HID + kc + c4 * 4);
            *(float4*)&As[r][c4 * 4] = v;
        }
        #pragma unroll
        for (int i = 0; i < 5; i++) {
            int f = tid + i * 256;       // 0..1279, covers 32*40 exactly
            int r = f / 40, c = f - r * 40;
            Bs[r][c] = W2[(size_t)(kc + r) * OUTD + c];
        }
        __syncthreads();

        #pragma unroll
        for (int kk = 0; kk < 32; kk++) {
            float a[4], b[5];
            #pragma unroll
            for (int i = 0; i < 4; i++) a[i] = As[trow * 4 + i][kk];
            #pragma unroll
            for (int j = 0; j < 5; j++) b[j] = Bs[kk][tcol * 5 + j];
            #pragma unroll
            for (int i = 0; i < 4; i++)
                #pragma unroll
                for (int j = 0; j < 5; j++) acc[i][j] = fmaf(a[i], b[j], acc[i][j]);
        }
        __syncthreads();
    }

    #pragma unroll
    for (int i = 0; i < 4; i++) {
        int m = m0 + trow * 4 + i;
        if (m < NN) {
            float di = g_dinv[m];
            #pragma unroll
            for (int j = 0; j < 5; j++)
                g_h2t[(size_t)m * OUTD + tcol * 5 + j] = acc[i][j] * di;
        }
    }
}

// ---------------- agg2 + bias + log_softmax ----------------
__global__ __launch_bounds__(256) void k_agg2(const float* __restrict__ b2,
                                              float* __restrict__ out) {
    int gw = (blockIdx.x * 256 + threadIdx.x) >> 5;
    int lane = threadIdx.x & 31;
    if (gw >= NN) return;
    bool hi = lane < 8;

    const float* self = g_h2t + (size_t)gw * OUTD;
    float a0 = self[lane];
    float a1v = hi ? self[32 + lane] : 0.f;

    int beg = g_rowptr[gw], end = g_rowptr[gw + 1];
    for (int e = beg; e < end; e++) {
        int s = g_col[e];
        const float* p = g_h2t + (size_t)s * OUTD;
        a0 += p[lane];
        if (hi) a1v += p[32 + lane];
    }

    float di = g_dinv[gw];
    float z0 = fmaf(di, a0, b2[lane]);
    float z1 = hi ? fmaf(di, a1v, b2[32 + lane]) : -3.4e38f;

    float mx = fmaxf(z0, z1);
    #pragma unroll
    for (int d = 16; d; d >>= 1) mx = fmaxf(mx, __shfl_xor_sync(0xffffffffu, mx, d));
    float s0 = expf(z0 - mx) + (hi ? expf(z1 - mx) : 0.f);
    #pragma unroll
    for (int d = 16; d; d >>= 1) s0 += __shfl_xor_sync(0xffffffffu, s0, d);
    float lse = mx + logf(s0);

    out[(size_t)gw * OUTD + lane] = z0 - lse;
    if (hi) out[(size_t)gw * OUTD + 32 + lane] = z1 - lse;
}

// ---------------- launch ----------------
extern "C" void kernel_launch(void* const* d_in, const int* in_sizes, int n_in,
                              void* d_out, int out_size) {
    const float* x  = (const float*)d_in[0];
    const int*   ei = (const int*)d_in[1];
    const float* W1 = (const float*)d_in[2];
    const float* b1 = (const float*)d_in[3];
    const float* W2 = (const float*)d_in[4];
    const float* b2 = (const float*)d_in[5];
    const int* src = ei;
    const int* dst = ei + NE;
    float* out = (float*)d_out;

    k_zero<<<(NN + 255) / 256, 256>>>();
    k_count<<<(NE + 255) / 256, 256>>>(dst);
    k_scan_reduce<<<NB1, 1024>>>();
    k_scan_mid<<<1, 128>>>();
    k_scan_final<<<NB1, 1024>>>();
    k_fill<<<(NE + 255) / 256, 256>>>(src, dst);

    k_gemm1<<<dim3((NN + 127) / 128, 2), 256>>>(x, W1);
    k_agg1<<<(NN * 32 + 255) / 256, 256>>>(b1);
    k_gemm2<<<(NN + 127) / 128, 256>>>(W2);
    k_agg2<<<(NN * 32 + 255) / 256, 256>>>(b2, out);
}

// round 6
// speedup vs baseline: 1.0974x; 1.0974x over previous
#include <cuda_runtime.h>

#define NN   100000
#define NE   800000
#define IND  128
#define HID  256
#define OUTD 40
#define NB1  98   // ceil(NN/1024)

// ---------------- scratch (static __device__ per harness rules) ----------------
__device__ int   g_cnt[NN];
__device__ int   g_rowptr[NN + 1];
__device__ int   g_cursor[NN];
__device__ int   g_col[NE];
__device__ float g_dinv[NN];
__device__ int   g_bsum[NB1];
__device__ int   g_boff[NB1];
__device__ float g_xa[(size_t)NN * IND];   // aggregated & normalized input
__device__ float g_a1[(size_t)NN * HID];   // layer-1 activations
__device__ float g_h2t[(size_t)NN * OUTD]; // (a1@W2)*dinv[row]

// ---------------- degree / CSR construction ----------------
__global__ void k_zero() {
    int i = blockIdx.x * blockDim.x + threadIdx.x;
    if (i < NN) g_cnt[i] = 0;
}

__global__ void k_count(const int* __restrict__ dst) {
    int e = blockIdx.x * blockDim.x + threadIdx.x;
    if (e < NE) atomicAdd(&g_cnt[dst[e]], 1);
}

__global__ void k_scan_reduce() {
    int i = blockIdx.x * 1024 + threadIdx.x;
    int v = (i < NN) ? g_cnt[i] : 0;
    #pragma unroll
    for (int d = 16; d; d >>= 1) v += __shfl_down_sync(0xffffffffu, v, d);
    __shared__ int sm[32];
    int lane = threadIdx.x & 31, wid = threadIdx.x >> 5;
    if (lane == 0) sm[wid] = v;
    __syncthreads();
    if (wid == 0) {
        int w = sm[lane];
        #pragma unroll
        for (int d = 16; d; d >>= 1) w += __shfl_down_sync(0xffffffffu, w, d);
        if (lane == 0) g_bsum[blockIdx.x] = w;
    }
}

__global__ void k_scan_mid() {
    __shared__ int sm[NB1];
    int t = threadIdx.x;
    if (t < NB1) sm[t] = g_bsum[t];
    __syncthreads();
    if (t == 0) {
        int run = 0;
        for (int i = 0; i < NB1; i++) { int c = sm[i]; sm[i] = run; run += c; }
        g_rowptr[NN] = run;
    }
    __syncthreads();
    if (t < NB1) g_boff[t] = sm[t];
}

__global__ void k_scan_final() {
    int i = blockIdx.x * 1024 + threadIdx.x;
    int lane = threadIdx.x & 31, wid = threadIdx.x >> 5;
    int c = (i < NN) ? g_cnt[i] : 0;
    int v = c;
    #pragma unroll
    for (int d = 1; d < 32; d <<= 1) {
        int t = __shfl_up_sync(0xffffffffu, v, d);
        if (lane >= d) v += t;
    }
    __shared__ int ws[32];
    if (lane == 31) ws[wid] = v;
    __syncthreads();
    if (wid == 0) {
        int w = ws[lane];
        #pragma unroll
        for (int d = 1; d < 32; d <<= 1) {
            int t = __shfl_up_sync(0xffffffffu, w, d);
            if (lane >= d) w += t;
        }
        ws[lane] = w;
    }
    __syncthreads();
    int woff = wid ? ws[wid - 1] : 0;
    int excl = v - c + woff + g_boff[blockIdx.x];
    if (i < NN) {
        g_rowptr[i] = excl;
        g_cursor[i] = excl;
        g_dinv[i]   = rsqrtf((float)(c + 1));  // +1 self-loop, deg >= 1
    }
}

__global__ void k_fill(const int* __restrict__ src, const int* __restrict__ dst) {
    int e = blockIdx.x * blockDim.x + threadIdx.x;
    if (e < NE) {
        int d = dst[e];
        int p = atomicAdd(&g_cursor[d], 1);
        g_col[p] = src[e];
    }
}

// ---------------- aggX: xa[d] = dinv[d]*(sum_in dinv[s]*x[s] + dinv[d]*x[d]) ----------
// warp per dst row; 128 floats = 1 float4 per lane.
__global__ __launch_bounds__(256) void k_aggx(const float* __restrict__ x) {
    int gw = (blockIdx.x * 256 + threadIdx.x) >> 5;
    int lane = threadIdx.x & 31;
    if (gw >= NN) return;

    const float4* x4 = (const float4*)x;
    float dg = g_dinv[gw];
    float4 xs = x4[(size_t)gw * 32 + lane];
    float4 acc;
    acc.x = dg * xs.x; acc.y = dg * xs.y; acc.z = dg * xs.z; acc.w = dg * xs.w;

    int beg = g_rowptr[gw], end = g_rowptr[gw + 1];
    for (int e = beg; e < end; e++) {
        int s = g_col[e];
        float ds = g_dinv[s];
        float4 v = x4[(size_t)s * 32 + lane];
        acc.x = fmaf(ds, v.x, acc.x);
        acc.y = fmaf(ds, v.y, acc.y);
        acc.z = fmaf(ds, v.z, acc.z);
        acc.w = fmaf(ds, v.w, acc.w);
    }

    float4 o;
    o.x = dg * acc.x; o.y = dg * acc.y; o.z = dg * acc.z; o.w = dg * acc.w;
    ((float4*)g_xa)[(size_t)gw * 32 + lane] = o;
}

// ---------------- GEMM1: a1 = relu(xa @ W1 + b1)  [NN,128]@[128,256] ----------------
__global__ __launch_bounds__(256) void k_gemm1(const float* __restrict__ W1,
                                               const float* __restrict__ b1) {
    __shared__ float As[128][32];   // [m][k]
    __shared__ float Bs[32][128];   // [k][n]
    const int m0 = blockIdx.x * 128;
    const int n0 = blockIdx.y * 128;
    const int tid = threadIdx.x;
    const int trow = tid >> 4;   // 0..15, 8 rows each
    const int tcol = tid & 15;   // 0..15, 8 cols each

    float acc[8][8];
    #pragma unroll
    for (int i = 0; i < 8; i++)
        #pragma unroll
        for (int j = 0; j < 8; j++) acc[i][j] = 0.f;

    for (int kc = 0; kc < IND; kc += 32) {
        #pragma unroll
        for (int i = 0; i < 4; i++) {
            int ff = tid + i * 256;
            int r = ff >> 3, c4 = ff & 7;
            int m = m0 + r;
            float4 v = make_float4(0.f, 0.f, 0.f, 0.f);
            if (m < NN) v = *(const float4*)(g_xa + (size_t)m * IND + kc + c4 * 4);
            *(float4*)&As[r][c4 * 4] = v;
        }
        #pragma unroll
        for (int i = 0; i < 4; i++) {
            int ff = tid + i * 256;
            int r = ff >> 5, c4 = ff & 31;
            *(float4*)&Bs[r][c4 * 4] =
                *(const float4*)(W1 + (size_t)(kc + r) * HID + n0 + c4 * 4);
        }
        __syncthreads();

        #pragma unroll
        for (int kk = 0; kk < 32; kk++) {
            float a[8], b[8];
            #pragma unroll
            for (int i = 0; i < 8; i++) a[i] = As[trow * 8 + i][kk];
            *(float4*)&b[0] = *(float4*)&Bs[kk][tcol * 8];
            *(float4*)&b[4] = *(float4*)&Bs[kk][tcol * 8 + 4];
            #pragma unroll
            for (int i = 0; i < 8; i++)
                #pragma unroll
                for (int j = 0; j < 8; j++) acc[i][j] = fmaf(a[i], b[j], acc[i][j]);
        }
        __syncthreads();
    }

    float4 bb0 = *(const float4*)(b1 + n0 + tcol * 8);
    float4 bb1 = *(const float4*)(b1 + n0 + tcol * 8 + 4);
    #pragma unroll
    for (int i = 0; i < 8; i++) {
        int m = m0 + trow * 8 + i;
        if (m < NN) {
            float4 o0, o1;
            o0.x = fmaxf(acc[i][0] + bb0.x, 0.f);
            o0.y = fmaxf(acc[i][1] + bb0.y, 0.f);
            o0.z = fmaxf(acc[i][2] + bb0.z, 0.f);
            o0.w = fmaxf(acc[i][3] + bb0.w, 0.f);
            o1.x = fmaxf(acc[i][4] + bb1.x, 0.f);
            o1.y = fmaxf(acc[i][5] + bb1.y, 0.f);
            o1.z = fmaxf(acc[i][6] + bb1.z, 0.f);
            o1.w = fmaxf(acc[i][7] + bb1.w, 0.f);
            float* outp = g_a1 + (size_t)m * HID + n0 + tcol * 8;
            *(float4*)(outp)     = o0;
            *(float4*)(outp + 4) = o1;
        }
    }
}

// ---------------- GEMM2: h2t = (a1 @ W2) * dinv[row]  [NN,256]@[256,40] ----------------
// Block: 256 rows x 40 cols. Thread: 8 rows x 5 cols. As pad 33 => conflict-free
// column reads (4 distinct banks, 8-way broadcast each).
__global__ __launch_bounds__(256) void k_gemm2(const float* __restrict__ W2) {
    __shared__ float As[256][33];
    __shared__ float Bs[32][40];
    const int m0 = blockIdx.x * 256;
    const int tid = threadIdx.x;
    const int trow = tid >> 3;   // 0..31, 8 rows each
    const int tcol = tid & 7;    // 0..7, 5 cols each

    float acc[8][5];
    #pragma unroll
    for (int i = 0; i < 8; i++)
        #pragma unroll
        for (int j = 0; j < 5; j++) acc[i][j] = 0.f;

    for (int kc = 0; kc < HID; kc += 32) {
        #pragma unroll
        for (int i = 0; i < 8; i++) {
            int ff = tid + i * 256;          // 0..2047 float4 slots
            int r = ff >> 3, c4 = ff & 7;    // r: row 0..255, c4: which float4 of 32 k
            int m = m0 + r;
            float4 v = make_float4(0.f, 0.f, 0.f, 0.f);
            if (m < NN) v = *(const float4*)(g_a1 + (size_t)m * HID + kc + c4 * 4);
            As[r][c4 * 4 + 0] = v.x;
            As[r][c4 * 4 + 1] = v.y;
            As[r][c4 * 4 + 2] = v.z;
            As[r][c4 * 4 + 3] = v.w;
        }
        #pragma unroll
        for (int i = 0; i < 5; i++) {
            int f = tid + i * 256;       // 0..1279, covers 32*40 exactly
            int r = f / 40, c = f - r * 40;
            Bs[r][c] = W2[(size_t)(kc + r) * OUTD + c];
        }
        __syncthreads();

        #pragma unroll
        for (int kk = 0; kk < 32; kk++) {
            float a[8], b[5];
            #pragma unroll
            for (int i = 0; i < 8; i++) a[i] = As[trow * 8 + i][kk];
            #pragma unroll
            for (int j = 0; j < 5; j++) b[j] = Bs[kk][tcol * 5 + j];
            #pragma unroll
            for (int i = 0; i < 8; i++)
                #pragma unroll
                for (int j = 0; j < 5; j++) acc[i][j] = fmaf(a[i], b[j], acc[i][j]);
        }
        __syncthreads();
    }

    #pragma unroll
    for (int i = 0; i < 8; i++) {
        int m = m0 + trow * 8 + i;
        if (m < NN) {
            float di = g_dinv[m];
            #pragma unroll
            for (int j = 0; j < 5; j++)
                g_h2t[(size_t)m * OUTD + tcol * 5 + j] = acc[i][j] * di;
        }
    }
}

// ---------------- agg2 + bias + log_softmax ----------------
__global__ __launch_bounds__(256) void k_agg2(const float* __restrict__ b2,
                                              float* __restrict__ out) {
    int gw = (blockIdx.x * 256 + threadIdx.x) >> 5;
    int lane = threadIdx.x & 31;
    if (gw >= NN) return;
    bool hi = lane < 8;

    const float* self = g_h2t + (size_t)gw * OUTD;
    float a0 = self[lane];
    float a1v = hi ? self[32 + lane] : 0.f;

    int beg = g_rowptr[gw], end = g_rowptr[gw + 1];
    for (int e = beg; e < end; e++) {
        int s = g_col[e];
        const float* p = g_h2t + (size_t)s * OUTD;
        a0 += p[lane];
        if (hi) a1v += p[32 + lane];
    }

    float di = g_dinv[gw];
    float z0 = fmaf(di, a0, b2[lane]);
    float z1 = hi ? fmaf(di, a1v, b2[32 + lane]) : -3.4e38f;

    float mx = fmaxf(z0, z1);
    #pragma unroll
    for (int d = 16; d; d >>= 1) mx = fmaxf(mx, __shfl_xor_sync(0xffffffffu, mx, d));
    float s0 = expf(z0 - mx) + (hi ? expf(z1 - mx) : 0.f);
    #pragma unroll
    for (int d = 16; d; d >>= 1) s0 += __shfl_xor_sync(0xffffffffu, s0, d);
    float lse = mx + logf(s0);

    out[(size_t)gw * OUTD + lane] = z0 - lse;
    if (hi) out[(size_t)gw * OUTD + 32 + lane] = z1 - lse;
}

// ---------------- launch ----------------
extern "C" void kernel_launch(void* const* d_in, const int* in_sizes, int n_in,
                              void* d_out, int out_size) {
    const float* x  = (const float*)d_in[0];
    const int*   ei = (const int*)d_in[1];
    const float* W1 = (const float*)d_in[2];
    const float* b1 = (const float*)d_in[3];
    const float* W2 = (const float*)d_in[4];
    const float* b2 = (const float*)d_in[5];
    const int* src = ei;
    const int* dst = ei + NE;
    float* out = (float*)d_out;

    k_zero<<<(NN + 255) / 256, 256>>>();
    k_count<<<(NE + 255) / 256, 256>>>(dst);
    k_scan_reduce<<<NB1, 1024>>>();
    k_scan_mid<<<1, 128>>>();
    k_scan_final<<<NB1, 1024>>>();
    k_fill<<<(NE + 255) / 256, 256>>>(src, dst);

    k_aggx<<<(NN * 32 + 255) / 256, 256>>>(x);
    k_gemm1<<<dim3((NN + 127) / 128, 2), 256>>>(W1, b1);
    k_gemm2<<<(NN + 255) / 256, 256>>>(W2);
    k_agg2<<<(NN * 32 + 255) / 256, 256>>>(b2, out);
}

// round 12
// speedup vs baseline: 1.6312x; 1.4865x over previous
#include <cuda_runtime.h>
#include <cuda_bf16.h>
#include <cstdint>

#define NN   100000
#define NE   800000
#define IND  128
#define HID  256
#define OUTD 40
#define NB1  98   // ceil(NN/1024)

// ---------------- scratch (static __device__ per harness rules) ----------------
__device__ int   g_cnt[NN];
__device__ int   g_rowptr[NN + 1];
__device__ int   g_cursor[NN];
__device__ int   g_col[NE];
__device__ float g_dinv[NN];
__device__ int   g_bsum[NB1];
__device__ int   g_boff[NB1];
__device__ __nv_bfloat16 g_xah[(size_t)NN * IND];   // aggregated input, bf16 hi
__device__ __nv_bfloat16 g_xal[(size_t)NN * IND];   // aggregated input, bf16 lo
__device__ __nv_bfloat16 g_w1th[(size_t)HID * IND]; // W1^T [n][k] bf16 hi
__device__ __nv_bfloat16 g_w1tl[(size_t)HID * IND]; // W1^T [n][k] bf16 lo
__device__ float g_a1[(size_t)NN * HID];   // layer-1 activations
__device__ float g_h2t[(size_t)NN * OUTD]; // (a1@W2)*dinv[row]

// ---------------- degree / CSR construction ----------------
__global__ void k_zero() {
    int i = blockIdx.x * blockDim.x + threadIdx.x;
    if (i < NN) g_cnt[i] = 0;
}

__global__ void k_count(const int* __restrict__ dst) {
    int e = blockIdx.x * blockDim.x + threadIdx.x;
    if (e < NE) atomicAdd(&g_cnt[dst[e]], 1);
}

__global__ void k_scan_reduce() {
    int i = blockIdx.x * 1024 + threadIdx.x;
    int v = (i < NN) ? g_cnt[i] : 0;
    #pragma unroll
    for (int d = 16; d; d >>= 1) v += __shfl_down_sync(0xffffffffu, v, d);
    __shared__ int sm[32];
    int lane = threadIdx.x & 31, wid = threadIdx.x >> 5;
    if (lane == 0) sm[wid] = v;
    __syncthreads();
    if (wid == 0) {
        int w = sm[lane];
        #pragma unroll
        for (int d = 16; d; d >>= 1) w += __shfl_down_sync(0xffffffffu, w, d);
        if (lane == 0) g_bsum[blockIdx.x] = w;
    }
}

__global__ void k_scan_mid() {
    __shared__ int sm[NB1];
    int t = threadIdx.x;
    if (t < NB1) sm[t] = g_bsum[t];
    __syncthreads();
    if (t == 0) {
        int run = 0;
        for (int i = 0; i < NB1; i++) { int c = sm[i]; sm[i] = run; run += c; }
        g_rowptr[NN] = run;
    }
    __syncthreads();
    if (t < NB1) g_boff[t] = sm[t];
}

__global__ void k_scan_final() {
    int i = blockIdx.x * 1024 + threadIdx.x;
    int lane = threadIdx.x & 31, wid = threadIdx.x >> 5;
    int c = (i < NN) ? g_cnt[i] : 0;
    int v = c;
    #pragma unroll
    for (int d = 1; d < 32; d <<= 1) {
        int t = __shfl_up_sync(0xffffffffu, v, d);
        if (lane >= d) v += t;
    }
    __shared__ int ws[32];
    if (lane == 31) ws[wid] = v;
    __syncthreads();
    if (wid == 0) {
        int w = ws[lane];
        #pragma unroll
        for (int d = 1; d < 32; d <<= 1) {
            int t = __shfl_up_sync(0xffffffffu, w, d);
            if (lane >= d) w += t;
        }
        ws[lane] = w;
    }
    __syncthreads();
    int woff = wid ? ws[wid - 1] : 0;
    int excl = v - c + woff + g_boff[blockIdx.x];
    if (i < NN) {
        g_rowptr[i] = excl;
        g_cursor[i] = excl;
        g_dinv[i]   = rsqrtf((float)(c + 1));  // +1 self-loop, deg >= 1
    }
}

__global__ void k_fill(const int* __restrict__ src, const int* __restrict__ dst) {
    int e = blockIdx.x * blockDim.x + threadIdx.x;
    if (e < NE) {
        int d = dst[e];
        int p = atomicAdd(&g_cursor[d], 1);
        g_col[p] = src[e];
    }
}

// ---------------- W1 transpose + bf16 split ----------------
__global__ void k_convw1(const float* __restrict__ W1) {
    int idx = blockIdx.x * 256 + threadIdx.x;   // 0..32767
    int n = idx & 255, k = idx >> 8;
    float v = W1[(size_t)k * HID + n];
    __nv_bfloat16 h = __float2bfloat16(v);
    g_w1th[(size_t)n * IND + k] = h;
    g_w1tl[(size_t)n * IND + k] = __float2bfloat16(v - __bfloat162float(h));
}

// ---------------- aggX: xa[d]=dinv[d]*(sum dinv[s]x[s] + dinv[d]x[d]), bf16 split out --
__global__ __launch_bounds__(256) void k_aggx(const float* __restrict__ x) {
    int gw = (blockIdx.x * 256 + threadIdx.x) >> 5;
    int lane = threadIdx.x & 31;
    if (gw >= NN) return;

    const float4* x4 = (const float4*)x;
    float dg = g_dinv[gw];
    float4 xs = x4[(size_t)gw * 32 + lane];
    float4 acc;
    acc.x = dg * xs.x; acc.y = dg * xs.y; acc.z = dg * xs.z; acc.w = dg * xs.w;

    int beg = g_rowptr[gw], end = g_rowptr[gw + 1];
    for (int e = beg; e < end; e++) {
        int s = g_col[e];
        float ds = g_dinv[s];
        float4 v = x4[(size_t)s * 32 + lane];
        acc.x = fmaf(ds, v.x, acc.x);
        acc.y = fmaf(ds, v.y, acc.y);
        acc.z = fmaf(ds, v.z, acc.z);
        acc.w = fmaf(ds, v.w, acc.w);
    }

    float ox = dg * acc.x, oy = dg * acc.y, oz = dg * acc.z, ow = dg * acc.w;
    __nv_bfloat16 hx = __float2bfloat16(ox), hy = __float2bfloat16(oy);
    __nv_bfloat16 hz = __float2bfloat16(oz), hw = __float2bfloat16(ow);
    __nv_bfloat162 h01, h23, l01, l23;
    h01.x = hx; h01.y = hy; h23.x = hz; h23.y = hw;
    l01.x = __float2bfloat16(ox - __bfloat162float(hx));
    l01.y = __float2bfloat16(oy - __bfloat162float(hy));
    l23.x = __float2bfloat16(oz - __bfloat162float(hz));
    l23.y = __float2bfloat16(ow - __bfloat162float(hw));
    size_t base = (size_t)gw * IND + lane * 4;
    *(__nv_bfloat162*)(g_xah + base)     = h01;
    *(__nv_bfloat162*)(g_xah + base + 2) = h23;
    *(__nv_bfloat162*)(g_xal + base)     = l01;
    *(__nv_bfloat162*)(g_xal + base + 2) = l23;
}

// ---------------- GEMM1 (mma.sync bf16 split): a1 = relu(xa @ W1 + b1) --------
// CTA 128x128 tile (grid.y=2 over N=256). K=128 in two 64-chunks in SMEM.
// 8 warps: 2 (m) x 4 (n); warp tile 64x32 = 4x4 m16n8k16 tiles; 3 mma per tile.
#define G1_STRIDE 72                              // 64 + 8 pad (bf16 units)
#define G1_ARR    (128 * G1_STRIDE)               // 9216 bf16 = 18432 B
#define G1_SMEM   (4 * G1_ARR * 2)                // 73728 B

#define MMA16816(c, a, b)                                                       \
    asm volatile("mma.sync.aligned.m16n8k16.row.col.f32.bf16.bf16.f32 "         \
        "{%0,%1,%2,%3}, {%4,%5,%6,%7}, {%8,%9}, {%0,%1,%2,%3};"                 \
        : "+f"((c)[0]), "+f"((c)[1]), "+f"((c)[2]), "+f"((c)[3])                \
        : "r"((a)[0]), "r"((a)[1]), "r"((a)[2]), "r"((a)[3]),                   \
          "r"((b)[0]), "r"((b)[1]))

__global__ __launch_bounds__(256, 2) void k_gemm1_mma(const float* __restrict__ b1) {
    extern __shared__ __nv_bfloat16 smb[];
    __nv_bfloat16* AH = smb;
    __nv_bfloat16* AL = smb + G1_ARR;
    __nv_bfloat16* BH = smb + 2 * G1_ARR;
    __nv_bfloat16* BL = smb + 3 * G1_ARR;

    const int tid = threadIdx.x;
    const int wid = tid >> 5, lane = tid & 31;
    const int g = lane >> 2, tg = lane & 3;
    const int wm = wid >> 2, wn = wid & 3;       // warp tile: (wm*64, wn*32)
    const int m0 = blockIdx.x * 128;
    const int n0 = blockIdx.y * 128;

    float acc[4][4][4];
    #pragma unroll
    for (int mi = 0; mi < 4; mi++)
        #pragma unroll
        for (int ni = 0; ni < 4; ni++)
            #pragma unroll
            for (int q = 0; q < 4; q++) acc[mi][ni][q] = 0.f;

    for (int kc = 0; kc < 2; kc++) {
        // ---- stage 64-wide K chunk ----
        #pragma unroll
        for (int i = 0; i < 4; i++) {
            int idx = tid + i * 256;             // 0..1023
            int r = idx >> 3, c8 = idx & 7;      // r: 0..127, c8: which 8-elem chunk
            size_t goff = (size_t)(m0 + r) * IND + kc * 64 + c8 * 8;
            uint4 z = make_uint4(0, 0, 0, 0);
            bool ok = (m0 + r) < NN;
            *(uint4*)(AH + r * G1_STRIDE + c8 * 8) = ok ? *(const uint4*)(g_xah + goff) : z;
            *(uint4*)(AL + r * G1_STRIDE + c8 * 8) = ok ? *(const uint4*)(g_xal + goff) : z;
            size_t boff = (size_t)(n0 + r) * IND + kc * 64 + c8 * 8;
            *(uint4*)(BH + r * G1_STRIDE + c8 * 8) = *(const uint4*)(g_w1th + boff);
            *(uint4*)(BL + r * G1_STRIDE + c8 * 8) = *(const uint4*)(g_w1tl + boff);
        }
        __syncthreads();

        // ---- 4 k-steps of 16 ----
        #pragma unroll
        for (int ks = 0; ks < 4; ks++) {
            int k0 = ks * 16;
            uint32_t af[4][4], bh[4][2], bl[4][2];
            #pragma unroll
            for (int ni = 0; ni < 4; ni++) {
                const __nv_bfloat16* p = BH + (wn * 32 + ni * 8 + g) * G1_STRIDE + k0 + 2 * tg;
                bh[ni][0] = *(const uint32_t*)(p);
                bh[ni][1] = *(const uint32_t*)(p + 8);
                const __nv_bfloat16* q = BL + (wn * 32 + ni * 8 + g) * G1_STRIDE + k0 + 2 * tg;
                bl[ni][0] = *(const uint32_t*)(q);
                bl[ni][1] = *(const uint32_t*)(q + 8);
            }
            #pragma unroll
            for (int mi = 0; mi < 4; mi++) {
                const __nv_bfloat16* p = AH + (wm * 64 + mi * 16 + g) * G1_STRIDE + k0 + 2 * tg;
                af[mi][0] = *(const uint32_t*)(p);
                af[mi][1] = *(const uint32_t*)(p + 8 * G1_STRIDE);
                af[mi][2] = *(const uint32_t*)(p + 8);
                af[mi][3] = *(const uint32_t*)(p + 8 * G1_STRIDE + 8);
            }
            #pragma unroll
            for (int mi = 0; mi < 4; mi++)
                #pragma unroll
                for (int ni = 0; ni < 4; ni++) {
                    MMA16816(acc[mi][ni], af[mi], bh[ni]);
                    MMA16816(acc[mi][ni], af[mi], bl[ni]);
                }
            #pragma unroll
            for (int mi = 0; mi < 4; mi++) {
                const __nv_bfloat16* p = AL + (wm * 64 + mi * 16 + g) * G1_STRIDE + k0 + 2 * tg;
                af[mi][0] = *(const uint32_t*)(p);
                af[mi][1] = *(const uint32_t*)(p + 8 * G1_STRIDE);
                af[mi][2] = *(const uint32_t*)(p + 8);
                af[mi][3] = *(const uint32_t*)(p + 8 * G1_STRIDE + 8);
            }
            #pragma unroll
            for (int mi = 0; mi < 4; mi++)
                #pragma unroll
                for (int ni = 0; ni < 4; ni++)
                    MMA16816(acc[mi][ni], af[mi], bh[ni]);
        }
        __syncthreads();
    }

    // ---- epilogue: bias + relu, float2 stores ----
    #pragma unroll
    for (int ni = 0; ni < 4; ni++) {
        int col = n0 + wn * 32 + ni * 8 + 2 * tg;
        float bz0 = __ldg(b1 + col), bz1 = __ldg(b1 + col + 1);
        #pragma unroll
        for (int mi = 0; mi < 4; mi++) {
            int row = m0 + wm * 64 + mi * 16 + g;
            if (row < NN) {
                float2 o;
                o.x = fmaxf(acc[mi][ni][0] + bz0, 0.f);
                o.y = fmaxf(acc[mi][ni][1] + bz1, 0.f);
                *(float2*)(g_a1 + (size_t)row * HID + col) = o;
            }
            if (row + 8 < NN) {
                float2 o;
                o.x = fmaxf(acc[mi][ni][2] + bz0, 0.f);
                o.y = fmaxf(acc[mi][ni][3] + bz1, 0.f);
                *(float2*)(g_a1 + (size_t)(row + 8) * HID + col) = o;
            }
        }
    }
}

// ---------------- GEMM2: h2t = (a1 @ W2) * dinv[row]  [NN,256]@[256,40] ----------------
__global__ __launch_bounds__(256) void k_gemm2(const float* __restrict__ W2) {
    __shared__ float As[256][33];
    __shared__ float Bs[32][40];
    const int m0 = blockIdx.x * 256;
    const int tid = threadIdx.x;
    const int trow = tid >> 3;   // 0..31, 8 rows each
    const int tcol = tid & 7;    // 0..7, 5 cols each

    float acc[8][5];
    #pragma unroll
    for (int i = 0; i < 8; i++)
        #pragma unroll
        for (int j = 0; j < 5; j++) acc[i][j] = 0.f;

    for (int kc = 0; kc < HID; kc += 32) {
        #pragma unroll
        for (int i = 0; i < 8; i++) {
            int ff = tid + i * 256;
            int r = ff >> 3, c4 = ff & 7;
            int m = m0 + r;
            float4 v = make_float4(0.f, 0.f, 0.f, 0.f);
            if (m < NN) v = *(const float4*)(g_a1 + (size_t)m * HID + kc + c4 * 4);
            As[r][c4 * 4 + 0] = v.x;
            As[r][c4 * 4 + 1] = v.y;
            As[r][c4 * 4 + 2] = v.z;
            As[r][c4 * 4 + 3] = v.w;
        }
        #pragma unroll
        for (int i = 0; i < 5; i++) {
            int f = tid + i * 256;
            int r = f / 40, c = f - r * 40;
            Bs[r][c] = W2[(size_t)(kc + r) * OUTD + c];
        }
        __syncthreads();

        #pragma unroll
        for (int kk = 0; kk < 32; kk++) {
            float a[8], b[5];
            #pragma unroll
            for (int i = 0; i < 8; i++) a[i] = As[trow * 8 + i][kk];
            #pragma unroll
            for (int j = 0; j < 5; j++) b[j] = Bs[kk][tcol * 5 + j];
            #pragma unroll
            for (int i = 0; i < 8; i++)
                #pragma unroll
                for (int j = 0; j < 5; j++) acc[i][j] = fmaf(a[i], b[j], acc[i][j]);
        }
        __syncthreads();
    }

    #pragma unroll
    for (int i = 0; i < 8; i++) {
        int m = m0 + trow * 8 + i;
        if (m < NN) {
            float di = g_dinv[m];
            #pragma unroll
            for (int j = 0; j < 5; j++)
                g_h2t[(size_t)m * OUTD + tcol * 5 + j] = acc[i][j] * di;
        }
    }
}

// ---------------- agg2 + bias + log_softmax ----------------
__global__ __launch_bounds__(256) void k_agg2(const float* __restrict__ b2,
                                              float* __restrict__ out) {
    int gw = (blockIdx.x * 256 + threadIdx.x) >> 5;
    int lane = threadIdx.x & 31;
    if (gw >= NN) return;
    bool hi = lane < 8;

    const float* self = g_h2t + (size_t)gw * OUTD;
    float a0 = self[lane];
    float a1v = hi ? self[32 + lane] : 0.f;

    int beg = g_rowptr[gw], end = g_rowptr[gw + 1];
    for (int e = beg; e < end; e++) {
        int s = g_col[e];
        const float* p = g_h2t + (size_t)s * OUTD;
        a0 += p[lane];
        if (hi) a1v += p[32 + lane];
    }

    float di = g_dinv[gw];
    float z0 = fmaf(di, a0, b2[lane]);
    float z1 = hi ? fmaf(di, a1v, b2[32 + lane]) : -3.4e38f;

    float mx = fmaxf(z0, z1);
    #pragma unroll
    for (int d = 16; d; d >>= 1) mx = fmaxf(mx, __shfl_xor_sync(0xffffffffu, mx, d));
    float s0 = expf(z0 - mx) + (hi ? expf(z1 - mx) : 0.f);
    #pragma unroll
    for (int d = 16; d; d >>= 1) s0 += __shfl_xor_sync(0xffffffffu, s0, d);
    float lse = mx + logf(s0);

    out[(size_t)gw * OUTD + lane] = z0 - lse;
    if (hi) out[(size_t)gw * OUTD + 32 + lane] = z1 - lse;
}

// ---------------- launch ----------------
extern "C" void kernel_launch(void* const* d_in, const int* in_sizes, int n_in,
                              void* d_out, int out_size) {
    const float* x  = (const float*)d_in[0];
    const int*   ei = (const int*)d_in[1];
    const float* W1 = (const float*)d_in[2];
    const float* b1 = (const float*)d_in[3];
    const float* W2 = (const float*)d_in[4];
    const float* b2 = (const float*)d_in[5];
    const int* src = ei;
    const int* dst = ei + NE;
    float* out = (float*)d_out;

    // Idempotent, capture-safe (not a stream op); no static guard per harness rules.
    cudaFuncSetAttribute(k_gemm1_mma, cudaFuncAttributeMaxDynamicSharedMemorySize, G1_SMEM);

    k_zero<<<(NN + 255) / 256, 256>>>();
    k_count<<<(NE + 255) / 256, 256>>>(dst);
    k_scan_reduce<<<NB1, 1024>>>();
    k_scan_mid<<<1, 128>>>();
    k_scan_final<<<NB1, 1024>>>();
    k_fill<<<(NE + 255) / 256, 256>>>(src, dst);

    k_convw1<<<128, 256>>>(W1);
    k_aggx<<<(NN * 32 + 255) / 256, 256>>>(x);
    k_gemm1_mma<<<dim3((NN + 127) / 128, 2), 256, G1_SMEM>>>(b1);
    k_gemm2<<<(NN + 255) / 256, 256>>>(W2);
    k_agg2<<<(NN * 32 + 255) / 256, 256>>>(b2, out);
}